// round 15
// baseline (speedup 1.0000x reference)
#include <cuda_runtime.h>
#include <cuda_fp16.h>
#include <cstddef>

#define NPTS 50000
#define C    96
#define G    6
#define S    16

typedef unsigned long long u64;

// packed fp32x2 helpers -------------------------------------------------------
__device__ __forceinline__ u64 fma2(u64 a, u64 b, u64 c) {
    u64 d;
    asm("fma.rn.f32x2 %0, %1, %2, %3;" : "=l"(d) : "l"(a), "l"(b), "l"(c));
    return d;
}
__device__ __forceinline__ float lo2(u64 v) { return __uint_as_float((unsigned)v); }
__device__ __forceinline__ float hi2(u64 v) { return __uint_as_float((unsigned)(v >> 32)); }
__device__ __forceinline__ float hsum2(u64 v) { return lo2(v) + hi2(v); }
__device__ __forceinline__ u64 dup2(float x) {
    u64 r;
    asm("mov.b64 %0, {%1, %1};" : "=l"(r) : "r"(__float_as_uint(x)));
    return r;
}
__device__ __forceinline__ __half2 h2u(unsigned u) { return *reinterpret_cast<__half2*>(&u); }
__device__ __forceinline__ float h2sum(__half2 a) {
    float2 f = __half22float2(a);
    return f.x + f.y;
}
// half2 (as uint) -> packed f32x2 (as u64)
__device__ __forceinline__ u64 h2tof2(unsigned h) {
    u64 r;
    asm("{\n\t"
        ".reg .b16 a,b;\n\t"
        ".reg .f32 x,y;\n\t"
        "mov.b32 {a,b}, %1;\n\t"
        "cvt.f32.f16 x,a;\n\t"
        "cvt.f32.f16 y,b;\n\t"
        "mov.b64 %0,{x,y};\n\t"
        "}" : "=l"(r) : "r"(h));
    return r;
}

// ---------------- scratch (static device globals) ----------------------------
__device__ float d_v   [NPTS * C];
__device__ float d_qW  [NPTS * G];
__device__ float d_kW  [NPTS * G];
__device__ float d_MT  [G * C];      // [g][cc] = (Wp2 @ Ww1)[cc][g]
__device__ float d_bM  [G];          // bp2 @ Ww1
__device__ float d_Wp2T[C * C];      // [co][ci]

// ---------------- k1: persistent QKV, fp16-weight / fp32-accum GEMM ----------
#define K1_TILE 88                    // 8 warps x 11 points
#define K1_THREADS 256
#define K1_GRID 304
#define K1_TILES ((NPTS + K1_TILE - 1) / K1_TILE)   // 569 <= 2*304
#define HS1 104                       // halves per fp16 row (96 + 8 pad)
// byte offsets
#define K1_FEAT 0                                   // 88*100*4 = 35200 (fp32)
#define K1_WST  35200                               // 96*104*2 = 19968 (fp16)
#define K1_TMP  55168                               // 88*104*2 = 18304 (fp16)
#define K1_WW1  73472                               // 6*104*2  = 1248  (fp16)
#define K1_SMEM 74720

__global__ __launch_bounds__(K1_THREADS, 2)
void k1_qkv(const float* __restrict__ feat,
            const float* __restrict__ Wq, const float* __restrict__ bq,
            const float* __restrict__ gq, const float* __restrict__ betaq,
            const float* __restrict__ Wk, const float* __restrict__ bk,
            const float* __restrict__ gk, const float* __restrict__ betak,
            const float* __restrict__ Wv, const float* __restrict__ bv,
            const float* __restrict__ Ww1,
            const float* __restrict__ Wp2, const float* __restrict__ bp2)
{
    const int tid = threadIdx.x;

    // precompute for k2 on the last block
    if (blockIdx.x == K1_GRID - 1) {
        for (int i = tid; i < C * C; i += K1_THREADS) {
            int co = i / C, ci = i % C;
            d_Wp2T[i] = __ldg(&Wp2[ci * C + co]);
        }
        for (int i = tid; i < G * C; i += K1_THREADS) {
            int g = i / C, cc = i % C;
            float s = 0.f;
            #pragma unroll 4
            for (int c2 = 0; c2 < C; c2++)
                s = fmaf(__ldg(&Wp2[cc * C + c2]), __ldg(&Ww1[c2 * G + g]), s);
            d_MT[i] = s;
        }
        if (tid < G) {
            float s = 0.f;
            for (int c2 = 0; c2 < C; c2++)
                s = fmaf(__ldg(&bp2[c2]), __ldg(&Ww1[c2 * G + tid]), s);
            d_bM[tid] = s;
        }
    }

    extern __shared__ __align__(16) unsigned char smraw[];
    float*  featS = (float*)(smraw + K1_FEAT);    // [p][k] stride 100 fp32
    __half* wstH  = (__half*)(smraw + K1_WST);    // [c][k] stride 104 fp16
    __half* tmpH  = (__half*)(smraw + K1_TMP);    // [p][c] stride 104 fp16
    __half* ww1H  = (__half*)(smraw + K1_WW1);    // [g][c] stride 104 fp16

    const float RS = rsqrtf(1.0f + 1e-5f);
    const int tx = tid & 31, ty = tid >> 5;   // lane = channel base, warp = point group

    for (int i = tid; i < C * G; i += K1_THREADS) {
        int c2 = i / G, g = i % G;
        ww1H[g * HS1 + c2] = __float2half(Ww1[i]);
    }

    for (int tile = blockIdx.x; tile < K1_TILES; tile += K1_GRID) {
        const int n0 = tile * K1_TILE;

        // stage feat tile fp32 (float4, coalesced; broadcast reads later)
        for (int i = tid; i < K1_TILE * 24; i += K1_THREADS) {
            int p = i / 24, kq = (i % 24) * 4;
            int n = n0 + p;
            float4 vv = (n < NPTS) ? *(const float4*)&feat[(size_t)n * C + kq]
                                   : make_float4(0.f, 0.f, 0.f, 0.f);
            *(float4*)&featS[p * 100 + kq] = vv;
        }

        for (int m = 0; m < 3; m++) {
            __syncthreads();
            const float* W = (m == 0) ? Wq : (m == 1) ? Wk : Wv;
            // stage transposed weights fp16
            for (int i = tid; i < C * 24; i += K1_THREADS) {
                int k = i / 24, cq = (i % 24) * 4;
                float4 w = *(const float4*)&W[k * C + cq];
                wstH[(cq + 0) * HS1 + k] = __float2half(w.x);
                wstH[(cq + 1) * HS1 + k] = __float2half(w.y);
                wstH[(cq + 2) * HS1 + k] = __float2half(w.z);
                wstH[(cq + 3) * HS1 + k] = __float2half(w.w);
            }
            __syncthreads();

            // GEMM: fp16 weights converted to f32x2 once per k8, fp32 accum
            u64 acc[11][3];
            #pragma unroll
            for (int pp = 0; pp < 11; pp++)
                #pragma unroll
                for (int cc = 0; cc < 3; cc++)
                    acc[pp][cc] = 0ull;

            #pragma unroll
            for (int k8 = 0; k8 < C; k8 += 8) {
                uint4 hb0 = *(const uint4*)&wstH[tx * HS1 + k8];
                uint4 hb1 = *(const uint4*)&wstH[(tx + 32) * HS1 + k8];
                uint4 hb2 = *(const uint4*)&wstH[(tx + 64) * HS1 + k8];
                u64 b0[4] = {h2tof2(hb0.x), h2tof2(hb0.y), h2tof2(hb0.z), h2tof2(hb0.w)};
                u64 b1[4] = {h2tof2(hb1.x), h2tof2(hb1.y), h2tof2(hb1.z), h2tof2(hb1.w)};
                u64 b2[4] = {h2tof2(hb2.x), h2tof2(hb2.y), h2tof2(hb2.z), h2tof2(hb2.w)};
                #pragma unroll
                for (int pp = 0; pp < 11; pp++) {
                    const float* ar = &featS[(ty * 11 + pp) * 100 + k8];
                    ulonglong2 aA = *(const ulonglong2*)ar;          // k8..k8+3
                    ulonglong2 aB = *(const ulonglong2*)(ar + 4);    // k8+4..k8+7
                    acc[pp][0] = fma2(aA.x, b0[0], acc[pp][0]);
                    acc[pp][0] = fma2(aA.y, b0[1], acc[pp][0]);
                    acc[pp][0] = fma2(aB.x, b0[2], acc[pp][0]);
                    acc[pp][0] = fma2(aB.y, b0[3], acc[pp][0]);
                    acc[pp][1] = fma2(aA.x, b1[0], acc[pp][1]);
                    acc[pp][1] = fma2(aA.y, b1[1], acc[pp][1]);
                    acc[pp][1] = fma2(aB.x, b1[2], acc[pp][1]);
                    acc[pp][1] = fma2(aB.y, b1[3], acc[pp][1]);
                    acc[pp][2] = fma2(aA.x, b2[0], acc[pp][2]);
                    acc[pp][2] = fma2(aA.y, b2[1], acc[pp][2]);
                    acc[pp][2] = fma2(aB.x, b2[2], acc[pp][2]);
                    acc[pp][2] = fma2(aB.y, b2[3], acc[pp][2]);
                }
            }

            if (m < 2) {
                const float* bb_ = (m == 0) ? bq : bk;
                const float* gg_ = (m == 0) ? gq : gk;
                const float* bt_ = (m == 0) ? betaq : betak;
                float bb[3], sc[3], bt[3];
                #pragma unroll
                for (int cc = 0; cc < 3; cc++) {
                    int ch = tx + 32 * cc;
                    bb[cc] = bb_[ch];
                    sc[cc] = gg_[ch] * RS;
                    bt[cc] = bt_[ch];
                }
                #pragma unroll
                for (int pp = 0; pp < 11; pp++) {
                    int p = ty * 11 + pp;
                    #pragma unroll
                    for (int cc = 0; cc < 3; cc++) {
                        float r = hsum2(acc[pp][cc]);
                        float v = fmaf(r + bb[cc], sc[cc], bt[cc]);
                        tmpH[p * HS1 + tx + 32 * cc] = __float2half(fmaxf(v, 0.f));
                    }
                }
                __syncthreads();
                // qW/kW reduction (fp16 dots; logits path, softmax-damped)
                float* dst = (m == 0) ? d_qW : d_kW;
                for (int t = tid; t < K1_TILE * G; t += K1_THREADS) {
                    int p = t / G, g = t % G;
                    int n = n0 + p;
                    if (n < NPTS) {
                        const uint4* hp = (const uint4*)(tmpH + p * HS1);
                        const uint4* wp = (const uint4*)(ww1H + g * HS1);
                        __half2 a0 = __float2half2_rn(0.f), a1 = a0;
                        #pragma unroll
                        for (int i = 0; i < 12; i++) {
                            uint4 hu = hp[i], wu = wp[i];
                            a0 = __hfma2(h2u(hu.x), h2u(wu.x), a0);
                            a1 = __hfma2(h2u(hu.y), h2u(wu.y), a1);
                            a0 = __hfma2(h2u(hu.z), h2u(wu.z), a0);
                            a1 = __hfma2(h2u(hu.w), h2u(wu.w), a1);
                        }
                        dst[(size_t)n * G + g] = h2sum(a0) + h2sum(a1);
                    }
                }
            } else {
                // v: direct coalesced stores from fp32 accumulators
                float bb[3];
                #pragma unroll
                for (int cc = 0; cc < 3; cc++) bb[cc] = bv[tx + 32 * cc];
                #pragma unroll
                for (int pp = 0; pp < 11; pp++) {
                    int n = n0 + ty * 11 + pp;
                    if (n < NPTS) {
                        #pragma unroll
                        for (int cc = 0; cc < 3; cc++)
                            d_v[(size_t)n * C + tx + 32 * cc] = hsum2(acc[pp][cc]) + bb[cc];
                    }
                }
            }
        }
        __syncthreads();   // tile boundary: protect featS before restage
    }
}

// ---------------- k2: warp-pod attention + fp16 smem (R11/R13, unchanged) ----
#define PTS 6
#define K2_THREADS (PTS * 32)       // 192
#define K2_GRID 304
#define K2_PODS (K2_GRID * PTS)
#define HST 104
#define OFF_WP2T 0
#define OFF_MT   19968
#define OFF_CST  21216
#define OFF_POD  21504
#define POD_B 5888
#define K2_SMEM (OFF_POD + PTS * POD_B)     // 56832 B

__global__ __launch_bounds__(K2_THREADS, 2)
void k2_attn(const float* __restrict__ coord,
             const int*   __restrict__ refidx,
             const float* __restrict__ Wp1, const float* __restrict__ bp1,
             const float* __restrict__ gp,  const float* __restrict__ betap,
             const float* __restrict__ bp2,
             const float* __restrict__ bw1, const float* __restrict__ gw,
             const float* __restrict__ betaw,
             const float* __restrict__ Ww2, const float* __restrict__ bw2,
             float* __restrict__ out)
{
    extern __shared__ __align__(16) unsigned char smraw[];
    __half* Wp2Th = (__half*)(smraw + OFF_WP2T);
    __half* MTh   = (__half*)(smraw + OFF_MT);
    float*  cst   = (float*)(smraw + OFF_CST);

    const int tid = threadIdx.x;
    const int pod = tid >> 5;
    const int l   = tid & 31;

    unsigned char* P = smraw + OFF_POD + pod * POD_B;
    __half* hs_h = (__half*)(P);
    __half* Hs_h = (__half*)(P + 3328);
    float*  ws   = (float*)(P + 4576);
    float*  us   = (float*)(P + 5088);
    float*  pos  = (float*)(P + 5472);
    float*  wsum = (float*)(P + 5728);
    int*    js_  = (int*)(P + 5760);

    const float RS = rsqrtf(1.0f + 1e-5f);

    for (int i = tid; i < C * 24; i += K2_THREADS) {
        int co = i / 24, ciq = (i % 24) * 4;
        float4 v = *(const float4*)&d_Wp2T[co * C + ciq];
        *(__half2*)&Wp2Th[co * HST + ciq]     = __floats2half2_rn(v.x, v.y);
        *(__half2*)&Wp2Th[co * HST + ciq + 2] = __floats2half2_rn(v.z, v.w);
    }
    for (int i = tid; i < G * C; i += K2_THREADS)
        MTh[(i / C) * HST + (i % C)] = __float2half(d_MT[i]);
    if      (tid < 36) cst[tid] = Ww2[tid];
    else if (tid < 42) cst[tid] = bw2[tid - 36];
    else if (tid < 48) cst[tid] = bw1[tid - 42];
    else if (tid < 54) cst[tid] = gw[tid - 48];
    else if (tid < 60) cst[tid] = betaw[tid - 54];
    else if (tid < 66) cst[tid] = d_bM[tid - 60];

    const int c0 = l, c1 = l + 32, c2 = l + 64;
    float w10[3], w11[3], w12[3], b1c[3], spc[3], btc[3], bp2v[3];
    #pragma unroll
    for (int p = 0; p < 3; p++) {
        int ch = l + 32 * p;
        w10[p] = __ldg(&Wp1[ch]);
        w11[p] = __ldg(&Wp1[C + ch]);
        w12[p] = __ldg(&Wp1[2 * C + ch]);
        b1c[p] = __ldg(&bp1[ch]);
        spc[p] = __ldg(&gp[ch]) * RS;
        btc[p] = __ldg(&betap[ch]);
        bp2v[p] = __ldg(&bp2[ch]);
    }
    const bool hi = (l >= 16);
    const int gc0 = hi ? 1 : 0, gc1 = hi ? 3 : 2, gc2 = hi ? 5 : 4;
    __syncthreads();

    for (int pt = blockIdx.x * PTS + pod; pt < NPTS; pt += K2_PODS) {
        const size_t n = (size_t)pt;

        if (l < 16) {
            int j = __ldg(&refidx[n * S + l]);
            js_[l] = j;
            float cx = __ldg(&coord[n * 3 + 0]);
            float cy = __ldg(&coord[n * 3 + 1]);
            float cz = __ldg(&coord[n * 3 + 2]);
            pos[l * 4 + 0] = __ldg(&coord[(size_t)j * 3 + 0]) - cx;
            pos[l * 4 + 1] = __ldg(&coord[(size_t)j * 3 + 1]) - cy;
            pos[l * 4 + 2] = __ldg(&coord[(size_t)j * 3 + 2]) - cz;
        }
        __syncwarp();

        #pragma unroll
        for (int s = 0; s < 16; s++) {
            float4 pp = *(const float4*)&pos[s * 4];
            #pragma unroll
            for (int p = 0; p < 3; p++) {
                float hv = fmaf(pp.x, w10[p], fmaf(pp.y, w11[p], fmaf(pp.z, w12[p], b1c[p])));
                hv = fmaxf(fmaf(hv, spc[p], btc[p]), 0.0f);
                hs_h[s * HST + l + 32 * p] = __float2half(hv);
            }
        }
        __syncwarp();

        #pragma unroll
        for (int p = 0; p < 3; p++) {
            int idx = l + 32 * p;
            int s = idx / 6, g = idx % 6;
            const uint4* hp = (const uint4*)(hs_h + s * HST);
            const uint4* mp = (const uint4*)(MTh + g * HST);
            __half2 a0 = __float2half2_rn(0.f), a1 = a0;
            #pragma unroll
            for (int i = 0; i < 12; i++) {
                uint4 hu = hp[i], mu = mp[i];
                a0 = __hfma2(h2u(hu.x), h2u(mu.x), a0);
                a1 = __hfma2(h2u(hu.y), h2u(mu.y), a1);
                a0 = __hfma2(h2u(hu.z), h2u(mu.z), a0);
                a1 = __hfma2(h2u(hu.w), h2u(mu.w), a1);
            }
            float2 f0 = __half22float2(a0), f1 = __half22float2(a1);
            float dot = (f0.x + f0.y) + (f1.x + f1.y);
            float kq = __ldg(&d_kW[(size_t)js_[s] * G + g]) - __ldg(&d_qW[n * G + g]);
            float tt = kq + dot + cst[60 + g] + cst[42 + g];
            us[idx] = fmaxf(fmaf(tt, cst[48 + g] * RS, cst[54 + g]), 0.0f);
        }
        __syncwarp();

        if (l < 24) {
            const int q = l / 6, g2 = l % 6;
            float lg[4];
            #pragma unroll
            for (int i = 0; i < 4; i++) {
                int s = q * 4 + i;
                float lv = cst[36 + g2];
                #pragma unroll
                for (int g = 0; g < 6; g++)
                    lv = fmaf(us[s * 6 + g], cst[g * 6 + g2], lv);
                lg[i] = lv;
            }
            float lm = fmaxf(fmaxf(lg[0], lg[1]), fmaxf(lg[2], lg[3]));
            float m1 = fmaxf(lm, __shfl_down_sync(0x00FFFFFF, lm, 12));
            float m  = fmaxf(m1, __shfl_down_sync(0x00FFFFFF, m1, 6));
            m = __shfl_sync(0x00FFFFFF, m, g2);
            float e[4];
            float sm = 0.f;
            #pragma unroll
            for (int i = 0; i < 4; i++) { e[i] = __expf(lg[i] - m); sm += e[i]; }
            float sm1 = sm + __shfl_down_sync(0x00FFFFFF, sm, 12);
            float smt = sm1 + __shfl_down_sync(0x00FFFFFF, sm1, 6);
            float inv = 1.0f / __shfl_sync(0x00FFFFFF, smt, g2);
            float accw = 0.f;
            #pragma unroll
            for (int i = 0; i < 4; i++) {
                int s = q * 4 + i;
                int jp1 = js_[s] + 1;
                float msk = (float)((jp1 > 0) - (jp1 < 0));
                float w = e[i] * inv * msk;
                ws[s * 8 + g2] = w;
                accw += w;
            }
            float a1r = accw + __shfl_down_sync(0x00FFFFFF, accw, 12);
            float at  = a1r + __shfl_down_sync(0x00FFFFFF, a1r, 6);
            if (l < 6) wsum[l] = at;
        }
        __syncwarp();

        u64 HA[3] = {0,0,0}, HB[3] = {0,0,0}, HC[3] = {0,0,0};
        float vs0 = 0.f, vs1 = 0.f, vs2 = 0.f;
        #pragma unroll
        for (int s = 0; s < 16; s++) {
            ulonglong2 w03 = *(const ulonglong2*)&ws[s * 8];
            u64 w45 = *(const u64*)&ws[s * 8 + 4];
            float h0 = __half2float(hs_h[s * HST + c0]);
            float h1 = __half2float(hs_h[s * HST + c1]);
            float h2 = __half2float(hs_h[s * HST + c2]);
            u64 h0d = dup2(h0), h1d = dup2(h1), h2d = dup2(h2);
            HA[0] = fma2(h0d, w03.x, HA[0]);
            HA[1] = fma2(h0d, w03.y, HA[1]);
            HA[2] = fma2(h0d, w45,   HA[2]);
            HB[0] = fma2(h1d, w03.x, HB[0]);
            HB[1] = fma2(h1d, w03.y, HB[1]);
            HB[2] = fma2(h1d, w45,   HB[2]);
            HC[0] = fma2(h2d, w03.x, HC[0]);
            HC[1] = fma2(h2d, w03.y, HC[1]);
            HC[2] = fma2(h2d, w45,   HC[2]);
            float wg0 = hi ? hi2(w03.x) : lo2(w03.x);
            float wg1 = hi ? hi2(w03.y) : lo2(w03.y);
            float wg2 = hi ? hi2(w45)   : lo2(w45);
            int j = js_[s];
            vs0 = fmaf(wg0, __ldg(&d_v[(size_t)j * C + c0]), vs0);
            vs1 = fmaf(wg1, __ldg(&d_v[(size_t)j * C + c1]), vs1);
            vs2 = fmaf(wg2, __ldg(&d_v[(size_t)j * C + c2]), vs2);
        }
        Hs_h[0 * HST + c0] = __float2half(lo2(HA[0]));
        Hs_h[1 * HST + c0] = __float2half(hi2(HA[0]));
        Hs_h[2 * HST + c0] = __float2half(lo2(HA[1]));
        Hs_h[3 * HST + c0] = __float2half(hi2(HA[1]));
        Hs_h[4 * HST + c0] = __float2half(lo2(HA[2]));
        Hs_h[5 * HST + c0] = __float2half(hi2(HA[2]));
        Hs_h[0 * HST + c1] = __float2half(lo2(HB[0]));
        Hs_h[1 * HST + c1] = __float2half(hi2(HB[0]));
        Hs_h[2 * HST + c1] = __float2half(lo2(HB[1]));
        Hs_h[3 * HST + c1] = __float2half(hi2(HB[1]));
        Hs_h[4 * HST + c1] = __float2half(lo2(HB[2]));
        Hs_h[5 * HST + c1] = __float2half(hi2(HB[2]));
        Hs_h[0 * HST + c2] = __float2half(lo2(HC[0]));
        Hs_h[1 * HST + c2] = __float2half(hi2(HC[0]));
        Hs_h[2 * HST + c2] = __float2half(lo2(HC[1]));
        Hs_h[3 * HST + c2] = __float2half(hi2(HC[1]));
        Hs_h[4 * HST + c2] = __float2half(lo2(HC[2]));
        Hs_h[5 * HST + c2] = __float2half(hi2(HC[2]));
        __syncwarp();

        float vsv[3] = {vs0, vs1, vs2};
        int   gcv[3] = {gc0, gc1, gc2};
        #pragma unroll
        for (int p = 0; p < 3; p++) {
            int cc_ = l + 32 * p;
            int gcp = gcv[p];
            const uint4* wp = (const uint4*)(Wp2Th + cc_ * HST);
            const uint4* hp = (const uint4*)(Hs_h + gcp * HST);
            __half2 b0 = __float2half2_rn(0.f), b1 = b0, b2 = b0, b3 = b0;
            #pragma unroll
            for (int i = 0; i < 12; i++) {
                uint4 wu = wp[i], hu = hp[i];
                b0 = __hfma2(h2u(wu.x), h2u(hu.x), b0);
                b1 = __hfma2(h2u(wu.y), h2u(hu.y), b1);
                b2 = __hfma2(h2u(wu.z), h2u(hu.z), b2);
                b3 = __hfma2(h2u(wu.w), h2u(hu.w), b3);
            }
            float2 f0 = __half22float2(b0), f1 = __half22float2(b1);
            float2 f2 = __half22float2(b2), f3 = __half22float2(b3);
            float dot = ((f0.x + f0.y) + (f1.x + f1.y)) + ((f2.x + f2.y) + (f3.x + f3.y));
            out[n * C + cc_] = fmaf(bp2v[p], wsum[gcp], vsv[p]) + dot;
        }
        __syncwarp();
    }
}

// ---------------- host launcher ---------------------------------------------
extern "C" void kernel_launch(void* const* d_in, const int* in_sizes, int n_in,
                              void* d_out, int out_size)
{
    bool dict = (in_sizes[2] == NPTS * S);

    const float* feat  = (const float*)d_in[0];
    const float* coord = (const float*)d_in[1];
    const int*   ref   = (const int*)d_in[dict ? 2 : 24];
    int wb = dict ? 3 : 2;
    const float* Wq    = (const float*)d_in[wb + 0];
    const float* bq    = (const float*)d_in[wb + 1];
    const float* gq    = (const float*)d_in[wb + 2];
    const float* betaq = (const float*)d_in[wb + 3];
    const float* Wk    = (const float*)d_in[wb + 4];
    const float* bk    = (const float*)d_in[wb + 5];
    const float* gk    = (const float*)d_in[wb + 6];
    const float* betak = (const float*)d_in[wb + 7];
    const float* Wv    = (const float*)d_in[wb + 8];
    const float* bv    = (const float*)d_in[wb + 9];
    const float* Wp1   = (const float*)d_in[wb + 10];
    const float* bp1   = (const float*)d_in[wb + 11];
    const float* gp    = (const float*)d_in[wb + 12];
    const float* betap = (const float*)d_in[wb + 13];
    const float* Wp2   = (const float*)d_in[wb + 14];
    const float* bp2   = (const float*)d_in[wb + 15];
    const float* Ww1   = (const float*)d_in[wb + 16];
    const float* bw1   = (const float*)d_in[wb + 17];
    const float* gw    = (const float*)d_in[wb + 18];
    const float* betaw = (const float*)d_in[wb + 19];
    const float* Ww2   = (const float*)d_in[wb + 20];
    const float* bw2   = (const float*)d_in[wb + 21];
    float* out = (float*)d_out;

    cudaFuncSetAttribute(k1_qkv,  cudaFuncAttributeMaxDynamicSharedMemorySize, K1_SMEM);
    cudaFuncSetAttribute(k2_attn, cudaFuncAttributeMaxDynamicSharedMemorySize, K2_SMEM);

    k1_qkv<<<K1_GRID, K1_THREADS, K1_SMEM>>>(
        feat, Wq, bq, gq, betaq, Wk, bk, gk, betak, Wv, bv, Ww1, Wp2, bp2);
    k2_attn<<<K2_GRID, K2_THREADS, K2_SMEM>>>(
        coord, ref, Wp1, bp1, gp, betap, bp2, bw1, gw, betaw, Ww2, bw2, out);
}

// round 16
// speedup vs baseline: 1.0118x; 1.0118x over previous
#include <cuda_runtime.h>
#include <cuda_fp16.h>
#include <cstddef>

#define NPTS 50000
#define C    96
#define G    6
#define S    16

typedef unsigned long long u64;

// packed fp32x2 helpers -------------------------------------------------------
__device__ __forceinline__ u64 fma2(u64 a, u64 b, u64 c) {
    u64 d;
    asm("fma.rn.f32x2 %0, %1, %2, %3;" : "=l"(d) : "l"(a), "l"(b), "l"(c));
    return d;
}
__device__ __forceinline__ float lo2(u64 v) { return __uint_as_float((unsigned)v); }
__device__ __forceinline__ float hi2(u64 v) { return __uint_as_float((unsigned)(v >> 32)); }
__device__ __forceinline__ float hsum2(u64 v) { return lo2(v) + hi2(v); }
__device__ __forceinline__ u64 dup2(float x) {
    u64 r;
    asm("mov.b64 %0, {%1, %1};" : "=l"(r) : "r"(__float_as_uint(x)));
    return r;
}
__device__ __forceinline__ __half2 h2u(unsigned u) { return *reinterpret_cast<__half2*>(&u); }
__device__ __forceinline__ float h2sum(__half2 a) {
    float2 f = __half22float2(a);
    return f.x + f.y;
}
__device__ __forceinline__ u64 h2tof2(unsigned h) {
    u64 r;
    asm("{\n\t"
        ".reg .b16 a,b;\n\t"
        ".reg .f32 x,y;\n\t"
        "mov.b32 {a,b}, %1;\n\t"
        "cvt.f32.f16 x,a;\n\t"
        "cvt.f32.f16 y,b;\n\t"
        "mov.b64 %0,{x,y};\n\t"
        "}" : "=l"(r) : "r"(h));
    return r;
}

// ---------------- scratch (static device globals) ----------------------------
__device__ float d_v   [NPTS * C];
__device__ float d_qW  [NPTS * G];
__device__ float d_kW  [NPTS * G];
__device__ float d_MT  [G * C];
__device__ float d_bM  [G];
__device__ float d_Wp2T[C * C];

// ---------------- k1: persistent QKV, weights staged once --------------------
#define K1_TILE 84                    // 7 warps x 12 points
#define K1_THREADS 224
#define K1_GRID 304
#define K1_TILES ((NPTS + K1_TILE - 1) / K1_TILE)   // 596 <= 2*304
#define HS1 104                       // halves per fp16 row
#define FS1 96                        // floats per featS row (broadcast reads)
// byte offsets
#define K1_FEAT 0                                   // 84*96*4  = 32256
#define K1_WST  32256                               // 3*96*104*2 = 59904
#define K1_TMP  92160                               // 84*104*2 = 17472
#define K1_WW1  109632                              // 6*104*2  = 1248
#define K1_SMEM 110880

__global__ __launch_bounds__(K1_THREADS, 2)
void k1_qkv(const float* __restrict__ feat,
            const float* __restrict__ Wq, const float* __restrict__ bq,
            const float* __restrict__ gq, const float* __restrict__ betaq,
            const float* __restrict__ Wk, const float* __restrict__ bk,
            const float* __restrict__ gk, const float* __restrict__ betak,
            const float* __restrict__ Wv, const float* __restrict__ bv,
            const float* __restrict__ Ww1,
            const float* __restrict__ Wp2, const float* __restrict__ bp2)
{
    const int tid = threadIdx.x;

    // precompute for k2 on the last block (it owns only 1 tile: 596 <= 607)
    if (blockIdx.x == K1_GRID - 1) {
        for (int i = tid; i < C * C; i += K1_THREADS) {
            int co = i / C, ci = i % C;
            d_Wp2T[i] = __ldg(&Wp2[ci * C + co]);
        }
        for (int i = tid; i < G * C; i += K1_THREADS) {
            int g = i / C, cc = i % C;
            float s = 0.f;
            #pragma unroll 4
            for (int c2 = 0; c2 < C; c2++)
                s = fmaf(__ldg(&Wp2[cc * C + c2]), __ldg(&Ww1[c2 * G + g]), s);
            d_MT[i] = s;
        }
        if (tid < G) {
            float s = 0.f;
            for (int c2 = 0; c2 < C; c2++)
                s = fmaf(__ldg(&bp2[c2]), __ldg(&Ww1[c2 * G + tid]), s);
            d_bM[tid] = s;
        }
    }

    extern __shared__ __align__(16) unsigned char smraw[];
    float*  featS = (float*)(smraw + K1_FEAT);    // [p][k] stride 96 fp32
    __half* wstH  = (__half*)(smraw + K1_WST);    // 3 x [c][k] stride 104 fp16
    __half* tmpH  = (__half*)(smraw + K1_TMP);    // [p][c] stride 104 fp16
    __half* ww1H  = (__half*)(smraw + K1_WW1);    // [g][c] stride 104 fp16

    const float RS = rsqrtf(1.0f + 1e-5f);
    const int tx = tid & 31, ty = tid >> 5;       // ty 0..6, 12 points each

    // ---- stage all weights ONCE ----
    for (int i = tid; i < C * G; i += K1_THREADS) {
        int c2 = i / G, g = i % G;
        ww1H[g * HS1 + c2] = __float2half(Ww1[i]);
    }
    for (int mm = 0; mm < 3; mm++) {
        const float* W = (mm == 0) ? Wq : (mm == 1) ? Wk : Wv;
        __half* wst = wstH + mm * (C * HS1);
        for (int i = tid; i < C * 24; i += K1_THREADS) {
            int k = i / 24, cq = (i % 24) * 4;
            float4 w = *(const float4*)&W[k * C + cq];
            wst[(cq + 0) * HS1 + k] = __float2half(w.x);
            wst[(cq + 1) * HS1 + k] = __float2half(w.y);
            wst[(cq + 2) * HS1 + k] = __float2half(w.z);
            wst[(cq + 3) * HS1 + k] = __float2half(w.w);
        }
    }
    __syncthreads();

    for (int tile = blockIdx.x; tile < K1_TILES; tile += K1_GRID) {
        const int n0 = tile * K1_TILE;

        // stage feat tile fp32 (coalesced; later reads are broadcast)
        for (int i = tid; i < K1_TILE * 24; i += K1_THREADS) {
            int p = i / 24, kq = (i % 24) * 4;
            int n = n0 + p;
            float4 vv = (n < NPTS) ? *(const float4*)&feat[(size_t)n * C + kq]
                                   : make_float4(0.f, 0.f, 0.f, 0.f);
            *(float4*)&featS[p * FS1 + kq] = vv;
        }
        __syncthreads();

        for (int m = 0; m < 3; m++) {
            const __half* wst = wstH + m * (C * HS1);

            u64 acc[12][3];
            #pragma unroll
            for (int pp = 0; pp < 12; pp++)
                #pragma unroll
                for (int cc = 0; cc < 3; cc++)
                    acc[pp][cc] = 0ull;

            #pragma unroll
            for (int k8 = 0; k8 < C; k8 += 8) {
                uint4 hb0 = *(const uint4*)&wst[tx * HS1 + k8];
                uint4 hb1 = *(const uint4*)&wst[(tx + 32) * HS1 + k8];
                uint4 hb2 = *(const uint4*)&wst[(tx + 64) * HS1 + k8];
                u64 b0[4] = {h2tof2(hb0.x), h2tof2(hb0.y), h2tof2(hb0.z), h2tof2(hb0.w)};
                u64 b1[4] = {h2tof2(hb1.x), h2tof2(hb1.y), h2tof2(hb1.z), h2tof2(hb1.w)};
                u64 b2[4] = {h2tof2(hb2.x), h2tof2(hb2.y), h2tof2(hb2.z), h2tof2(hb2.w)};
                #pragma unroll
                for (int pp = 0; pp < 12; pp++) {
                    const float* ar = &featS[(ty * 12 + pp) * FS1 + k8];
                    ulonglong2 aA = *(const ulonglong2*)ar;
                    ulonglong2 aB = *(const ulonglong2*)(ar + 4);
                    acc[pp][0] = fma2(aA.x, b0[0], acc[pp][0]);
                    acc[pp][0] = fma2(aA.y, b0[1], acc[pp][0]);
                    acc[pp][0] = fma2(aB.x, b0[2], acc[pp][0]);
                    acc[pp][0] = fma2(aB.y, b0[3], acc[pp][0]);
                    acc[pp][1] = fma2(aA.x, b1[0], acc[pp][1]);
                    acc[pp][1] = fma2(aA.y, b1[1], acc[pp][1]);
                    acc[pp][1] = fma2(aB.x, b1[2], acc[pp][1]);
                    acc[pp][1] = fma2(aB.y, b1[3], acc[pp][1]);
                    acc[pp][2] = fma2(aA.x, b2[0], acc[pp][2]);
                    acc[pp][2] = fma2(aA.y, b2[1], acc[pp][2]);
                    acc[pp][2] = fma2(aB.x, b2[2], acc[pp][2]);
                    acc[pp][2] = fma2(aB.y, b2[3], acc[pp][2]);
                }
            }

            if (m < 2) {
                const float* bb_ = (m == 0) ? bq : bk;
                const float* gg_ = (m == 0) ? gq : gk;
                const float* bt_ = (m == 0) ? betaq : betak;
                float bb[3], sc[3], bt[3];
                #pragma unroll
                for (int cc = 0; cc < 3; cc++) {
                    int ch = tx + 32 * cc;
                    bb[cc] = bb_[ch];
                    sc[cc] = gg_[ch] * RS;
                    bt[cc] = bt_[ch];
                }
                #pragma unroll
                for (int pp = 0; pp < 12; pp++) {
                    int p = ty * 12 + pp;
                    #pragma unroll
                    for (int cc = 0; cc < 3; cc++) {
                        float r = hsum2(acc[pp][cc]);
                        float v = fmaf(r + bb[cc], sc[cc], bt[cc]);
                        tmpH[p * HS1 + tx + 32 * cc] = __float2half(fmaxf(v, 0.f));
                    }
                }
                __syncthreads();
                float* dst = (m == 0) ? d_qW : d_kW;
                for (int t = tid; t < K1_TILE * G; t += K1_THREADS) {
                    int p = t / G, g = t % G;
                    int n = n0 + p;
                    if (n < NPTS) {
                        const uint4* hp = (const uint4*)(tmpH + p * HS1);
                        const uint4* wp = (const uint4*)(ww1H + g * HS1);
                        __half2 a0 = __float2half2_rn(0.f), a1 = a0;
                        #pragma unroll
                        for (int i = 0; i < 12; i++) {
                            uint4 hu = hp[i], wu = wp[i];
                            a0 = __hfma2(h2u(hu.x), h2u(wu.x), a0);
                            a1 = __hfma2(h2u(hu.y), h2u(wu.y), a1);
                            a0 = __hfma2(h2u(hu.z), h2u(wu.z), a0);
                            a1 = __hfma2(h2u(hu.w), h2u(wu.w), a1);
                        }
                        dst[(size_t)n * G + g] = h2sum(a0) + h2sum(a1);
                    }
                }
                __syncthreads();   // protect tmpH before next m writes it
            } else {
                float bb[3];
                #pragma unroll
                for (int cc = 0; cc < 3; cc++) bb[cc] = bv[tx + 32 * cc];
                #pragma unroll
                for (int pp = 0; pp < 12; pp++) {
                    int n = n0 + ty * 12 + pp;
                    if (n < NPTS) {
                        #pragma unroll
                        for (int cc = 0; cc < 3; cc++)
                            d_v[(size_t)n * C + tx + 32 * cc] = hsum2(acc[pp][cc]) + bb[cc];
                    }
                }
            }
        }
        __syncthreads();   // tile boundary: protect featS before restage
    }
}

// ---------------- k2: warp-pod attention, 2 points/iter, paired P8 -----------
#define PTS 6
#define K2_THREADS (PTS * 32)       // 192
#define K2_GRID 304
#define K2_PODS (K2_GRID * PTS)
#define NPAIRS (NPTS / 2)           // 25000
#define HST 104
#define OFF_WP2T 0
#define OFF_MT   19968
#define OFF_CST  21216
#define OFF_POD  21504
// pod: hs 0..3328 | HsA 3328..4576 | HsB 4576..5824 | ws 5824..6336 |
//      us 6336..6720 | pos 6720..6976 | wsum 6976..7008 | js 7008..7072 | pad
#define POD_B 7104
#define K2_SMEM (OFF_POD + PTS * POD_B)     // 64128 B

__global__ __launch_bounds__(K2_THREADS, 2)
void k2_attn(const float* __restrict__ coord,
             const int*   __restrict__ refidx,
             const float* __restrict__ Wp1, const float* __restrict__ bp1,
             const float* __restrict__ gp,  const float* __restrict__ betap,
             const float* __restrict__ bp2,
             const float* __restrict__ bw1, const float* __restrict__ gw,
             const float* __restrict__ betaw,
             const float* __restrict__ Ww2, const float* __restrict__ bw2,
             float* __restrict__ out)
{
    extern __shared__ __align__(16) unsigned char smraw[];
    __half* Wp2Th = (__half*)(smraw + OFF_WP2T);
    __half* MTh   = (__half*)(smraw + OFF_MT);
    float*  cst   = (float*)(smraw + OFF_CST);

    const int tid = threadIdx.x;
    const int pod = tid >> 5;
    const int l   = tid & 31;

    unsigned char* P = smraw + OFF_POD + pod * POD_B;
    __half* hs_h = (__half*)(P);
    __half* HsA  = (__half*)(P + 3328);
    __half* HsB  = (__half*)(P + 4576);
    float*  ws   = (float*)(P + 5824);
    float*  us   = (float*)(P + 6336);
    float*  pos  = (float*)(P + 6720);
    float*  wsum = (float*)(P + 6976);
    int*    js_  = (int*)(P + 7008);

    const float RS = rsqrtf(1.0f + 1e-5f);

    for (int i = tid; i < C * 24; i += K2_THREADS) {
        int co = i / 24, ciq = (i % 24) * 4;
        float4 v = *(const float4*)&d_Wp2T[co * C + ciq];
        *(__half2*)&Wp2Th[co * HST + ciq]     = __floats2half2_rn(v.x, v.y);
        *(__half2*)&Wp2Th[co * HST + ciq + 2] = __floats2half2_rn(v.z, v.w);
    }
    for (int i = tid; i < G * C; i += K2_THREADS)
        MTh[(i / C) * HST + (i % C)] = __float2half(d_MT[i]);
    if      (tid < 36) cst[tid] = Ww2[tid];
    else if (tid < 42) cst[tid] = bw2[tid - 36];
    else if (tid < 48) cst[tid] = bw1[tid - 42];
    else if (tid < 54) cst[tid] = gw[tid - 48];
    else if (tid < 60) cst[tid] = betaw[tid - 54];
    else if (tid < 66) cst[tid] = d_bM[tid - 60];

    const int c0 = l, c1 = l + 32, c2 = l + 64;
    float w10[3], w11[3], w12[3], b1c[3], spc[3], btc[3], bp2v[3];
    #pragma unroll
    for (int p = 0; p < 3; p++) {
        int ch = l + 32 * p;
        w10[p] = __ldg(&Wp1[ch]);
        w11[p] = __ldg(&Wp1[C + ch]);
        w12[p] = __ldg(&Wp1[2 * C + ch]);
        b1c[p] = __ldg(&bp1[ch]);
        spc[p] = __ldg(&gp[ch]) * RS;
        btc[p] = __ldg(&betap[ch]);
        bp2v[p] = __ldg(&bp2[ch]);
    }
    const bool hi = (l >= 16);
    const int gc0 = hi ? 1 : 0, gc1 = hi ? 3 : 2, gc2 = hi ? 5 : 4;
    const int gcv[3] = {gc0, gc1, gc2};
    __syncthreads();

    for (int pi = blockIdx.x * PTS + pod; pi < NPAIRS; pi += K2_PODS) {
        float vsH[2][3], wsH[2][3];

        #pragma unroll
        for (int half = 0; half < 2; half++) {
            const size_t n = (size_t)(2 * pi + half);
            __half* Hs_h = half ? HsB : HsA;

            // W: indices + relative positions (lanes 0-15)
            if (l < 16) {
                int j = __ldg(&refidx[n * S + l]);
                js_[l] = j;
                float cx = __ldg(&coord[n * 3 + 0]);
                float cy = __ldg(&coord[n * 3 + 1]);
                float cz = __ldg(&coord[n * 3 + 2]);
                pos[l * 4 + 0] = __ldg(&coord[(size_t)j * 3 + 0]) - cx;
                pos[l * 4 + 1] = __ldg(&coord[(size_t)j * 3 + 1]) - cy;
                pos[l * 4 + 2] = __ldg(&coord[(size_t)j * 3 + 2]) - cz;
            }
            __syncwarp();

            // P3
            #pragma unroll
            for (int s = 0; s < 16; s++) {
                float4 pp = *(const float4*)&pos[s * 4];
                #pragma unroll
                for (int p = 0; p < 3; p++) {
                    float hv = fmaf(pp.x, w10[p], fmaf(pp.y, w11[p], fmaf(pp.z, w12[p], b1c[p])));
                    hv = fmaxf(fmaf(hv, spc[p], btc[p]), 0.0f);
                    hs_h[s * HST + l + 32 * p] = __float2half(hv);
                }
            }
            __syncwarp();

            // P4
            #pragma unroll
            for (int p = 0; p < 3; p++) {
                int idx = l + 32 * p;
                int s = idx / 6, g = idx % 6;
                const uint4* hp = (const uint4*)(hs_h + s * HST);
                const uint4* mp = (const uint4*)(MTh + g * HST);
                __half2 a0 = __float2half2_rn(0.f), a1 = a0;
                #pragma unroll
                for (int i = 0; i < 12; i++) {
                    uint4 hu = hp[i], mu = mp[i];
                    a0 = __hfma2(h2u(hu.x), h2u(mu.x), a0);
                    a1 = __hfma2(h2u(hu.y), h2u(mu.y), a1);
                    a0 = __hfma2(h2u(hu.z), h2u(mu.z), a0);
                    a1 = __hfma2(h2u(hu.w), h2u(mu.w), a1);
                }
                float2 f0 = __half22float2(a0), f1 = __half22float2(a1);
                float dot = (f0.x + f0.y) + (f1.x + f1.y);
                float kq = __ldg(&d_kW[(size_t)js_[s] * G + g]) - __ldg(&d_qW[n * G + g]);
                float tt = kq + dot + cst[60 + g] + cst[42 + g];
                us[idx] = fmaxf(fmaf(tt, cst[48 + g] * RS, cst[54 + g]), 0.0f);
            }
            __syncwarp();

            // P5+P6 fused softmax (lanes 0-23)
            if (l < 24) {
                const int q = l / 6, g2 = l % 6;
                float lg[4];
                #pragma unroll
                for (int i = 0; i < 4; i++) {
                    int s = q * 4 + i;
                    float lv = cst[36 + g2];
                    #pragma unroll
                    for (int g = 0; g < 6; g++)
                        lv = fmaf(us[s * 6 + g], cst[g * 6 + g2], lv);
                    lg[i] = lv;
                }
                float lm = fmaxf(fmaxf(lg[0], lg[1]), fmaxf(lg[2], lg[3]));
                float m1 = fmaxf(lm, __shfl_down_sync(0x00FFFFFF, lm, 12));
                float m  = fmaxf(m1, __shfl_down_sync(0x00FFFFFF, m1, 6));
                m = __shfl_sync(0x00FFFFFF, m, g2);
                float e[4];
                float sm = 0.f;
                #pragma unroll
                for (int i = 0; i < 4; i++) { e[i] = __expf(lg[i] - m); sm += e[i]; }
                float sm1 = sm + __shfl_down_sync(0x00FFFFFF, sm, 12);
                float smt = sm1 + __shfl_down_sync(0x00FFFFFF, sm1, 6);
                float inv = 1.0f / __shfl_sync(0x00FFFFFF, smt, g2);
                float accw = 0.f;
                #pragma unroll
                for (int i = 0; i < 4; i++) {
                    int s = q * 4 + i;
                    int jp1 = js_[s] + 1;
                    float msk = (float)((jp1 > 0) - (jp1 < 0));
                    float w = e[i] * inv * msk;
                    ws[s * 8 + g2] = w;
                    accw += w;
                }
                float a1r = accw + __shfl_down_sync(0x00FFFFFF, accw, 12);
                float at  = a1r + __shfl_down_sync(0x00FFFFFF, a1r, 6);
                if (l < 6) wsum[l] = at;
            }
            __syncwarp();

            // P7: H accumulation + vsum
            u64 HA[3] = {0,0,0}, HB[3] = {0,0,0}, HC[3] = {0,0,0};
            float vs0 = 0.f, vs1 = 0.f, vs2 = 0.f;
            #pragma unroll
            for (int s = 0; s < 16; s++) {
                ulonglong2 w03 = *(const ulonglong2*)&ws[s * 8];
                u64 w45 = *(const u64*)&ws[s * 8 + 4];
                float h0 = __half2float(hs_h[s * HST + c0]);
                float h1 = __half2float(hs_h[s * HST + c1]);
                float h2 = __half2float(hs_h[s * HST + c2]);
                u64 h0d = dup2(h0), h1d = dup2(h1), h2d = dup2(h2);
                HA[0] = fma2(h0d, w03.x, HA[0]);
                HA[1] = fma2(h0d, w03.y, HA[1]);
                HA[2] = fma2(h0d, w45,   HA[2]);
                HB[0] = fma2(h1d, w03.x, HB[0]);
                HB[1] = fma2(h1d, w03.y, HB[1]);
                HB[2] = fma2(h1d, w45,   HB[2]);
                HC[0] = fma2(h2d, w03.x, HC[0]);
                HC[1] = fma2(h2d, w03.y, HC[1]);
                HC[2] = fma2(h2d, w45,   HC[2]);
                float wg0 = hi ? hi2(w03.x) : lo2(w03.x);
                float wg1 = hi ? hi2(w03.y) : lo2(w03.y);
                float wg2 = hi ? hi2(w45)   : lo2(w45);
                int j = js_[s];
                vs0 = fmaf(wg0, __ldg(&d_v[(size_t)j * C + c0]), vs0);
                vs1 = fmaf(wg1, __ldg(&d_v[(size_t)j * C + c1]), vs1);
                vs2 = fmaf(wg2, __ldg(&d_v[(size_t)j * C + c2]), vs2);
            }
            Hs_h[0 * HST + c0] = __float2half(lo2(HA[0]));
            Hs_h[1 * HST + c0] = __float2half(hi2(HA[0]));
            Hs_h[2 * HST + c0] = __float2half(lo2(HA[1]));
            Hs_h[3 * HST + c0] = __float2half(hi2(HA[1]));
            Hs_h[4 * HST + c0] = __float2half(lo2(HA[2]));
            Hs_h[5 * HST + c0] = __float2half(hi2(HA[2]));
            Hs_h[0 * HST + c1] = __float2half(lo2(HB[0]));
            Hs_h[1 * HST + c1] = __float2half(hi2(HB[0]));
            Hs_h[2 * HST + c1] = __float2half(lo2(HB[1]));
            Hs_h[3 * HST + c1] = __float2half(hi2(HB[1]));
            Hs_h[4 * HST + c1] = __float2half(lo2(HB[2]));
            Hs_h[5 * HST + c1] = __float2half(hi2(HB[2]));
            Hs_h[0 * HST + c2] = __float2half(lo2(HC[0]));
            Hs_h[1 * HST + c2] = __float2half(hi2(HC[0]));
            Hs_h[2 * HST + c2] = __float2half(lo2(HC[1]));
            Hs_h[3 * HST + c2] = __float2half(hi2(HC[1]));
            Hs_h[4 * HST + c2] = __float2half(lo2(HC[2]));
            Hs_h[5 * HST + c2] = __float2half(hi2(HC[2]));
            vsH[half][0] = vs0; vsH[half][1] = vs1; vsH[half][2] = vs2;
            wsH[half][0] = wsum[gc0]; wsH[half][1] = wsum[gc1]; wsH[half][2] = wsum[gc2];
            __syncwarp();   // Hs stores visible; pod buffers safe for next half
        }

        // P8 paired: Wp2T rows loaded once, applied to both points
        const size_t nA = (size_t)(2 * pi), nB = nA + 1;
        #pragma unroll
        for (int p = 0; p < 3; p++) {
            int cc_ = l + 32 * p;
            int gcp = gcv[p];
            const uint4* wp  = (const uint4*)(Wp2Th + cc_ * HST);
            const uint4* hpA = (const uint4*)(HsA + gcp * HST);
            const uint4* hpB = (const uint4*)(HsB + gcp * HST);
            __half2 a0 = __float2half2_rn(0.f), a1 = a0, b0 = a0, b1 = a0;
            #pragma unroll
            for (int i = 0; i < 12; i++) {
                uint4 wu = wp[i];
                uint4 ha = hpA[i];
                uint4 hb = hpB[i];
                a0 = __hfma2(h2u(wu.x), h2u(ha.x), a0);
                a1 = __hfma2(h2u(wu.y), h2u(ha.y), a1);
                a0 = __hfma2(h2u(wu.z), h2u(ha.z), a0);
                a1 = __hfma2(h2u(wu.w), h2u(ha.w), a1);
                b0 = __hfma2(h2u(wu.x), h2u(hb.x), b0);
                b1 = __hfma2(h2u(wu.y), h2u(hb.y), b1);
                b0 = __hfma2(h2u(wu.z), h2u(hb.z), b0);
                b1 = __hfma2(h2u(wu.w), h2u(hb.w), b1);
            }
            float dotA = h2sum(a0) + h2sum(a1);
            float dotB = h2sum(b0) + h2sum(b1);
            out[nA * C + cc_] = fmaf(bp2v[p], wsH[0][p], vsH[0][p]) + dotA;
            out[nB * C + cc_] = fmaf(bp2v[p], wsH[1][p], vsH[1][p]) + dotB;
        }
        __syncwarp();   // protect HsA/HsB before next pair overwrites
    }
}

// ---------------- host launcher ---------------------------------------------
extern "C" void kernel_launch(void* const* d_in, const int* in_sizes, int n_in,
                              void* d_out, int out_size)
{
    bool dict = (in_sizes[2] == NPTS * S);

    const float* feat  = (const float*)d_in[0];
    const float* coord = (const float*)d_in[1];
    const int*   ref   = (const int*)d_in[dict ? 2 : 24];
    int wb = dict ? 3 : 2;
    const float* Wq    = (const float*)d_in[wb + 0];
    const float* bq    = (const float*)d_in[wb + 1];
    const float* gq    = (const float*)d_in[wb + 2];
    const float* betaq = (const float*)d_in[wb + 3];
    const float* Wk    = (const float*)d_in[wb + 4];
    const float* bk    = (const float*)d_in[wb + 5];
    const float* gk    = (const float*)d_in[wb + 6];
    const float* betak = (const float*)d_in[wb + 7];
    const float* Wv    = (const float*)d_in[wb + 8];
    const float* bv    = (const float*)d_in[wb + 9];
    const float* Wp1   = (const float*)d_in[wb + 10];
    const float* bp1   = (const float*)d_in[wb + 11];
    const float* gp    = (const float*)d_in[wb + 12];
    const float* betap = (const float*)d_in[wb + 13];
    const float* Wp2   = (const float*)d_in[wb + 14];
    const float* bp2   = (const float*)d_in[wb + 15];
    const float* Ww1   = (const float*)d_in[wb + 16];
    const float* bw1   = (const float*)d_in[wb + 17];
    const float* gw    = (const float*)d_in[wb + 18];
    const float* betaw = (const float*)d_in[wb + 19];
    const float* Ww2   = (const float*)d_in[wb + 20];
    const float* bw2   = (const float*)d_in[wb + 21];
    float* out = (float*)d_out;

    cudaFuncSetAttribute(k1_qkv,  cudaFuncAttributeMaxDynamicSharedMemorySize, K1_SMEM);
    cudaFuncSetAttribute(k2_attn, cudaFuncAttributeMaxDynamicSharedMemorySize, K2_SMEM);

    k1_qkv<<<K1_GRID, K1_THREADS, K1_SMEM>>>(
        feat, Wq, bq, gq, betaq, Wk, bk, gk, betak, Wv, bv, Ww1, Wp2, bp2);
    k2_attn<<<K2_GRID, K2_THREADS, K2_SMEM>>>(
        coord, ref, Wp1, bp1, gp, betap, bp2, bw1, gw, betaw, Ww2, bw2, out);
}